// round 14
// baseline (speedup 1.0000x reference)
#include <cuda_runtime.h>
#include <math.h>

static constexpr int kT = 5, kB = 512, kNA = 16, kS = 64, kA = 16;
static constexpr int kHID = 64, kH = 4, kFD = 256, kLAT = 128;
static constexpr int kN = kB * kNA;
static constexpr int kFIN = 80;

// -------- scratch (static device globals) --------
__device__ float g_y   [(size_t)kB * kT * 4 * kFD];
__device__ float g_seq [(size_t)kB * kT * kFD];
__device__ float g_kv  [(size_t)kB * kT * 2 * kFD];
__device__ float g_q4  [(size_t)kB * kFD];
__device__ float g_ctx4[(size_t)kB * kFD];
__device__ float g_feat[(size_t)kB * kFD];
__device__ float g_blog[(size_t)kB * kS];
__device__ float g_v1  [2 * 4 * kFD];
__device__ float g_u0  [2 * 4 * kFIN];
__device__ float g_w0t [kFIN * kFD];
__device__ float g_sigp[(size_t)kT * kB * kFD];

// ===================================================================
// Prep: v1 + w0t + u0 + sigproj GEMM. grid = 251. (unchanged)
// ===================================================================
__global__ __launch_bounds__(256)
void prep_kernel(const float* __restrict__ w1, const float* __restrict__ asrc1,
                 const float* __restrict__ adst1, const float* __restrict__ w0,
                 const float* __restrict__ asrc0, const float* __restrict__ adst0,
                 const float* __restrict__ signals,
                 float* __restrict__ v1, float* __restrict__ w0t,
                 float* __restrict__ u0, float* __restrict__ sigp) {
    int bid = blockIdx.x, tid = threadIdx.x;
    if (bid < 8) {
        int idx = bid * 256 + tid;
        int which = idx >> 10;
        int h = (idx >> 8) & 3;
        int k = idx & 255;
        const float* a = which ? adst1 : asrc1;
        float acc = 0.f;
#pragma unroll
        for (int c = 0; c < 64; c++)
            acc += a[h * 64 + c] * w1[(size_t)(h * 64 + c) * kFD + k];
        v1[which * 1024 + h * 256 + k] = acc;
        return;
    }
    if (bid < 88) {
        int c = bid - 8;
        w0t[(size_t)c * kFD + tid] = w0[(size_t)tid * kFIN + c];
        return;
    }
    if (bid < 91) {
        int idx = (bid - 88) * 256 + tid;
        if (idx >= 640) return;
        int which = idx / 320;
        int r = idx % 320;
        int h = r / 80, f = r % 80;
        const float* a = which ? adst0 : asrc0;
        float acc = 0.f;
#pragma unroll
        for (int c = 0; c < 64; c++)
            acc += a[h * 64 + c] * w0[(size_t)(h * 64 + c) * kFIN + f];
        u0[idx] = acc;
        return;
    }
    {
        __shared__ float sigs[16][64];
        int r0 = (bid - 91) * 16;
#pragma unroll
        for (int i = 0; i < 4; i++) {
            int idx = tid + i * 256;
            sigs[idx >> 6][idx & 63] = signals[(size_t)(r0 + (idx >> 6)) * kS + (idx & 63)];
        }
        __syncthreads();
        float acc[16];
#pragma unroll
        for (int i = 0; i < 16; i++) acc[i] = 0.f;
        for (int c = 0; c < 64; c++) {
            float w = w0[(size_t)tid * kFIN + c];
#pragma unroll
            for (int i = 0; i < 16; i++) acc[i] += sigs[i][c] * w;
        }
#pragma unroll
        for (int i = 0; i < 16; i++)
            sigp[(size_t)(r0 + i) * kFD + tid] = acc[i];
    }
}

// ===================================================================
// GNN phase 1: one block per (t, g). v1 read via __ldg (L1-hot) — no
// smem staging (saves 8KB/block -> higher residency).
// ===================================================================
__global__ __launch_bounds__(256)
void gnn_phase1(const float* __restrict__ signals, const float* __restrict__ nact,
                const float* __restrict__ w0t, const float* __restrict__ u0,
                const float* __restrict__ bias0, const float* __restrict__ v1,
                const float* __restrict__ sigp, float* __restrict__ y) {
    __shared__ float acts[16][16];
    __shared__ float sig[64];
    __shared__ float us[320], ud[320];
    __shared__ float es0[16][4], ed0[16][4];
    __shared__ float alpha0[16][16][4];
    __shared__ float beta[16][4][16];
    __shared__ float gam[16][4];
    __shared__ float x1s[16][256];
    __shared__ float es1[16][4], ed1s[4], alpha1[16][4];

    int bid = blockIdx.x;
    int t = bid >> 9;
    int g = bid & 511;
    int tid = threadIdx.x;

    float Wa[16];
#pragma unroll
    for (int k = 0; k < 16; k++) Wa[k] = w0t[(size_t)(64 + k) * kFD + tid];
    float b0 = bias0[tid];
    float sp = sigp[(size_t)bid * kFD + tid];

    acts[tid >> 4][tid & 15] = nact[((size_t)t * kB + g) * (kNA * kA) + tid];
    if (tid < 64) sig[tid] = signals[((size_t)t * kB + g) * kS + tid];
#pragma unroll
    for (int i = 0; i < 2; i++) {
        int f = tid + i * 256;
        if (f < 320) { us[f] = u0[f]; ud[f] = u0[320 + f]; }
    }
    __syncthreads();

    if (tid < 128) {
        int which = tid >> 6;
        int p = tid & 63;
        int j = p >> 2, h = p & 3;
        const float* u = which ? ud : us;
        float e = 0.f;
#pragma unroll
        for (int k = 0; k < 16; k++) e += acts[j][k] * u[h * 80 + 64 + k];
        if (j == 0) {
#pragma unroll
            for (int c = 0; c < 64; c++) e += sig[c] * u[h * 80 + c];
        }
        if (which) ed0[j][h] = e; else es0[j][h] = e;
    }
    __syncthreads();

    if (tid < 64) {
        int n = tid >> 2, h = tid & 3;
        float base = ed0[n][h];
        float ev[16];
        float mx = -1e30f;
#pragma unroll
        for (int j = 0; j < 16; j++) {
            float e = es0[j][h] + base;
            e = e > 0.f ? e : 0.2f * e;
            ev[j] = e;
            mx = fmaxf(mx, e);
        }
        float sum = 0.f;
#pragma unroll
        for (int j = 0; j < 16; j++) { ev[j] = __expf(ev[j] - mx); sum += ev[j]; }
        float inv = 1.f / sum;
#pragma unroll
        for (int j = 0; j < 16; j++) alpha0[n][j][h] = ev[j] * inv;
    }
    __syncthreads();

    {
        int n = tid >> 4, h = (tid >> 2) & 3, kg = tid & 3;
        float bacc[4] = {0.f, 0.f, 0.f, 0.f};
#pragma unroll
        for (int j = 0; j < 16; j++) {
            float a = alpha0[n][j][h];
#pragma unroll
            for (int kk = 0; kk < 4; kk++) bacc[kk] += a * acts[j][kg * 4 + kk];
        }
#pragma unroll
        for (int kk = 0; kk < 4; kk++) beta[n][h][kg * 4 + kk] = bacc[kk];
        if (kg == 0) gam[n][h] = alpha0[n][0][h];
    }
    __syncthreads();

    int hd = tid >> 6;
    float x1r[16];
    {
#pragma unroll
        for (int n = 0; n < 16; n++) {
            float acc = gam[n][hd] * sp;
#pragma unroll
            for (int k = 0; k < 16; k++) acc += beta[n][hd][k] * Wa[k];
            acc = fmaxf(acc + b0, 0.f);
            x1r[n] = acc;
            x1s[n][tid] = acc;
        }
    }
    __syncthreads();

    {
        int p = tid >> 2, q = tid & 3;
        int j = p >> 2, h = p & 3;
        float acc = 0.f;
#pragma unroll
        for (int c = q * 64; c < q * 64 + 64; c++)
            acc += x1s[j][c] * __ldg(&v1[h * 256 + c]);
        acc += __shfl_xor_sync(0xffffffffu, acc, 1);
        acc += __shfl_xor_sync(0xffffffffu, acc, 2);
        if (q == 0) es1[j][h] = acc;
    }
    if (tid < 32) {
        int h = tid >> 3, q = tid & 7;
        float acc = 0.f;
#pragma unroll
        for (int c = q * 32; c < q * 32 + 32; c++)
            acc += x1s[0][c] * __ldg(&v1[1024 + h * 256 + c]);
        acc += __shfl_xor_sync(0xffffffffu, acc, 1);
        acc += __shfl_xor_sync(0xffffffffu, acc, 2);
        acc += __shfl_xor_sync(0xffffffffu, acc, 4);
        if (q == 0) ed1s[h] = acc;
    }
    __syncthreads();

    if (tid < 4) {
        int h = tid;
        float base = ed1s[h];
        float ev[16];
        float mx = -1e30f;
#pragma unroll
        for (int j = 0; j < 16; j++) {
            float e = es1[j][h] + base;
            e = e > 0.f ? e : 0.2f * e;
            ev[j] = e;
            mx = fmaxf(mx, e);
        }
        float sum = 0.f;
#pragma unroll
        for (int j = 0; j < 16; j++) { ev[j] = __expf(ev[j] - mx); sum += ev[j]; }
        float inv = 1.f / sum;
#pragma unroll
        for (int j = 0; j < 16; j++) alpha1[j][h] = ev[j] * inv;
    }
    __syncthreads();

#pragma unroll
    for (int h = 0; h < 4; h++) {
        float acc = 0.f;
#pragma unroll
        for (int j = 0; j < 16; j++) acc += alpha1[j][h] * x1r[j];
        y[(((size_t)g * kT + t) * 4 + h) * kFD + tid] = acc;
    }
}

// ===================================================================
// TF32 mma helpers
// ===================================================================
__device__ __forceinline__ unsigned f2tf(float x) {
    unsigned u;
    asm("cvt.rna.tf32.f32 %0, %1;" : "=r"(u) : "f"(x));
    return u;
}

// ---------------- 128x64 tile, K-chunk 32, XOR-swizzled (R13, for proj) ----
#define IA(b,r,c4) ((b)*4096 + (r)*32 + 4*((c4) ^ ((r)&7)))
#define IB(b,r,c4) ((b)*2048 + (r)*32 + 4*((c4) ^ ((r)&7)))

__device__ __forceinline__
void tf32_tile128(const float* __restrict__ A, int lda,
                  const float* __restrict__ Wt, const float* __restrict__ bias,
                  float* __restrict__ C, int ldc, int row0, int relu,
                  unsigned* sA, unsigned* sB) {
    int tid = threadIdx.x;
    int lane = tid & 31, warp = tid >> 5;
    int wm = warp & 3, wn = warp >> 2;
    int g4 = lane >> 2, l4 = lane & 3;

    float c[2][4][4];
#pragma unroll
    for (int mt = 0; mt < 2; mt++)
#pragma unroll
        for (int nt = 0; nt < 4; nt++)
#pragma unroll
            for (int i = 0; i < 4; i++) c[mt][nt][i] = 0.f;

#pragma unroll
    for (int i = 0; i < 4; i++) {
        int idx = tid + i * 256;
        int r = idx >> 3, c4 = idx & 7;
        float4 v = *(const float4*)&A[(size_t)(row0 + r) * lda + c4 * 4];
        unsigned* p = &sA[IA(0, r, c4)];
        p[0] = f2tf(v.x); p[1] = f2tf(v.y); p[2] = f2tf(v.z); p[3] = f2tf(v.w);
    }
#pragma unroll
    for (int i = 0; i < 2; i++) {
        int idx = tid + i * 256;
        int r = idx >> 3, c4 = idx & 7;
        float4 w = *(const float4*)&Wt[(size_t)r * 256 + c4 * 4];
        unsigned* p = &sB[IB(0, r, c4)];
        p[0] = f2tf(w.x); p[1] = f2tf(w.y); p[2] = f2tf(w.z); p[3] = f2tf(w.w);
    }
    __syncthreads();

    for (int ch = 0; ch < 8; ch++) {
        int buf = ch & 1;
        float4 pa[4], pw[2];
        if (ch < 7) {
            int k0 = (ch + 1) * 32;
#pragma unroll
            for (int i = 0; i < 4; i++) {
                int idx = tid + i * 256;
                int r = idx >> 3, c4 = idx & 7;
                pa[i] = *(const float4*)&A[(size_t)(row0 + r) * lda + k0 + c4 * 4];
            }
#pragma unroll
            for (int i = 0; i < 2; i++) {
                int idx = tid + i * 256;
                int r = idx >> 3, c4 = idx & 7;
                pw[i] = *(const float4*)&Wt[(size_t)r * 256 + k0 + c4 * 4];
            }
        }
#pragma unroll
        for (int kk = 0; kk < 4; kk++) {
            unsigned af[2][4], bf[4][2];
#pragma unroll
            for (int mt = 0; mt < 2; mt++) {
                int ar = wm * 32 + mt * 16 + g4;
                af[mt][0] = sA[IA(buf, ar,     kk * 2    ) + l4];
                af[mt][1] = sA[IA(buf, ar + 8, kk * 2    ) + l4];
                af[mt][2] = sA[IA(buf, ar,     kk * 2 + 1) + l4];
                af[mt][3] = sA[IA(buf, ar + 8, kk * 2 + 1) + l4];
            }
#pragma unroll
            for (int nt = 0; nt < 4; nt++) {
                int br = wn * 32 + nt * 8 + g4;
                bf[nt][0] = sB[IB(buf, br, kk * 2    ) + l4];
                bf[nt][1] = sB[IB(buf, br, kk * 2 + 1) + l4];
            }
#pragma unroll
            for (int mt = 0; mt < 2; mt++)
#pragma unroll
                for (int nt = 0; nt < 4; nt++) {
                    asm volatile(
                        "mma.sync.aligned.m16n8k8.row.col.f32.tf32.tf32.f32 "
                        "{%0,%1,%2,%3}, {%4,%5,%6,%7}, {%8,%9}, {%0,%1,%2,%3};"
                        : "+f"(c[mt][nt][0]), "+f"(c[mt][nt][1]),
                          "+f"(c[mt][nt][2]), "+f"(c[mt][nt][3])
                        : "r"(af[mt][0]), "r"(af[mt][1]), "r"(af[mt][2]), "r"(af[mt][3]),
                          "r"(bf[nt][0]), "r"(bf[nt][1]));
                }
        }
        if (ch < 7) {
            int nb = buf ^ 1;
#pragma unroll
            for (int i = 0; i < 4; i++) {
                int idx = tid + i * 256;
                int r = idx >> 3, c4 = idx & 7;
                unsigned* p = &sA[IA(nb, r, c4)];
                p[0] = f2tf(pa[i].x); p[1] = f2tf(pa[i].y);
                p[2] = f2tf(pa[i].z); p[3] = f2tf(pa[i].w);
            }
#pragma unroll
            for (int i = 0; i < 2; i++) {
                int idx = tid + i * 256;
                int r = idx >> 3, c4 = idx & 7;
                unsigned* p = &sB[IB(nb, r, c4)];
                p[0] = f2tf(pw[i].x); p[1] = f2tf(pw[i].y);
                p[2] = f2tf(pw[i].z); p[3] = f2tf(pw[i].w);
            }
        }
        __syncthreads();
    }

#pragma unroll
    for (int mt = 0; mt < 2; mt++) {
        int r = row0 + wm * 32 + mt * 16 + g4;
#pragma unroll
        for (int nt = 0; nt < 4; nt++) {
            int cc = wn * 32 + nt * 8 + 2 * l4;
            float b0v = bias[cc], b1v = bias[cc + 1];
            float v0 = c[mt][nt][0] + b0v, v1 = c[mt][nt][1] + b1v;
            float v2 = c[mt][nt][2] + b0v, v3 = c[mt][nt][3] + b1v;
            if (relu) {
                v0 = fmaxf(v0, 0.f); v1 = fmaxf(v1, 0.f);
                v2 = fmaxf(v2, 0.f); v3 = fmaxf(v3, 0.f);
            }
            C[(size_t)r * ldc + cc] = v0;
            C[(size_t)r * ldc + cc + 1] = v1;
            C[(size_t)(r + 8) * ldc + cc] = v2;
            C[(size_t)(r + 8) * ldc + cc + 1] = v3;
        }
    }
}

// ---------------- 128x128 tile, K-chunk 16, 20-pad smem (for qkv) ----------
// sA/sB: 2 x 128 x 20 u32 = 20KB each (40KB total). Banks: 20r%32 distinct
// over 8 consecutive g4-rows -> conflict-free frag LDS.
#define PD(b,r,c) (((b)*128 + (r))*20 + (c))

__device__ __forceinline__
void tf32_tile128x128(const float* __restrict__ A, int lda,
                      const float* __restrict__ Wt, const float* __restrict__ bias,
                      float* __restrict__ C, int ldc, int row0, int relu,
                      unsigned* sA, unsigned* sB) {
    int tid = threadIdx.x;
    int lane = tid & 31, warp = tid >> 5;
    int wm = warp & 3, wn = warp >> 2;     // 4 x 2 warps; warp tile 32 x 64
    int g4 = lane >> 2, l4 = lane & 3;
    int r2 = tid >> 1, c42 = (tid & 1) * 2;   // loads: 2 f4/thread: rows tid>>1

    float c[2][8][4];
#pragma unroll
    for (int mt = 0; mt < 2; mt++)
#pragma unroll
        for (int nt = 0; nt < 8; nt++)
#pragma unroll
            for (int i = 0; i < 4; i++) c[mt][nt][i] = 0.f;

    // chunk 0: A/B 128x16 each; 2 f4 per thread each
#pragma unroll
    for (int i = 0; i < 2; i++) {
        float4 v = *(const float4*)&A[(size_t)(row0 + r2) * lda + (c42 + i) * 4];
        unsigned* p = &sA[PD(0, r2, (c42 + i) * 4)];
        p[0] = f2tf(v.x); p[1] = f2tf(v.y); p[2] = f2tf(v.z); p[3] = f2tf(v.w);
        float4 w = *(const float4*)&Wt[(size_t)r2 * 256 + (c42 + i) * 4];
        unsigned* q = &sB[PD(0, r2, (c42 + i) * 4)];
        q[0] = f2tf(w.x); q[1] = f2tf(w.y); q[2] = f2tf(w.z); q[3] = f2tf(w.w);
    }
    __syncthreads();

    for (int ch = 0; ch < 16; ch++) {
        int buf = ch & 1;
        float4 pa[2], pw[2];
        if (ch < 15) {
            int k0 = (ch + 1) * 16;
#pragma unroll
            for (int i = 0; i < 2; i++) {
                pa[i] = *(const float4*)&A[(size_t)(row0 + r2) * lda + k0 + (c42 + i) * 4];
                pw[i] = *(const float4*)&Wt[(size_t)r2 * 256 + k0 + (c42 + i) * 4];
            }
        }
#pragma unroll
        for (int kk = 0; kk < 2; kk++) {
            unsigned af[2][4], bf[8][2];
#pragma unroll
            for (int mt = 0; mt < 2; mt++) {
                int ar = wm * 32 + mt * 16 + g4;
                af[mt][0] = sA[PD(buf, ar,     kk * 8 + l4)];
                af[mt][1] = sA[PD(buf, ar + 8, kk * 8 + l4)];
                af[mt][2] = sA[PD(buf, ar,     kk * 8 + l4 + 4)];
                af[mt][3] = sA[PD(buf, ar + 8, kk * 8 + l4 + 4)];
            }
#pragma unroll
            for (int nt = 0; nt < 8; nt++) {
                int br = wn * 64 + nt * 8 + g4;
                bf[nt][0] = sB[PD(buf, br, kk * 8 + l4)];
                bf[nt][1] = sB[PD(buf, br, kk * 8 + l4 + 4)];
            }
#pragma unroll
            for (int mt = 0; mt < 2; mt++)
#pragma unroll
                for (int nt = 0; nt < 8; nt++) {
                    asm volatile(
                        "mma.sync.aligned.m16n8k8.row.col.f32.tf32.tf32.f32 "
                        "{%0,%1,%2,%3}, {%4,%5,%6,%7}, {%8,%9}, {%0,%1,%2,%3};"
                        : "+f"(c[mt][nt][0]), "+f"(c[mt][nt][1]),
                          "+f"(c[mt][nt][2]), "+f"(c[mt][nt][3])
                        : "r"(af[mt][0]), "r"(af[mt][1]), "r"(af[mt][2]), "r"(af[mt][3]),
                          "r"(bf[nt][0]), "r"(bf[nt][1]));
                }
        }
        if (ch < 15) {
            int nb = buf ^ 1;
#pragma unroll
            for (int i = 0; i < 2; i++) {
                unsigned* p = &sA[PD(nb, r2, (c42 + i) * 4)];
                p[0] = f2tf(pa[i].x); p[1] = f2tf(pa[i].y);
                p[2] = f2tf(pa[i].z); p[3] = f2tf(pa[i].w);
                unsigned* q = &sB[PD(nb, r2, (c42 + i) * 4)];
                q[0] = f2tf(pw[i].x); q[1] = f2tf(pw[i].y);
                q[2] = f2tf(pw[i].z); q[3] = f2tf(pw[i].w);
            }
        }
        __syncthreads();
    }

#pragma unroll
    for (int mt = 0; mt < 2; mt++) {
        int r = row0 + wm * 32 + mt * 16 + g4;
#pragma unroll
        for (int nt = 0; nt < 8; nt++) {
            int cc = wn * 64 + nt * 8 + 2 * l4;
            float b0v = bias[cc], b1v = bias[cc + 1];
            float v0 = c[mt][nt][0] + b0v, v1 = c[mt][nt][1] + b1v;
            float v2 = c[mt][nt][2] + b0v, v3 = c[mt][nt][3] + b1v;
            if (relu) {
                v0 = fmaxf(v0, 0.f); v1 = fmaxf(v1, 0.f);
                v2 = fmaxf(v2, 0.f); v3 = fmaxf(v3, 0.f);
            }
            C[(size_t)r * ldc + cc] = v0;
            C[(size_t)r * ldc + cc + 1] = v1;
            C[(size_t)(r + 8) * ldc + cc] = v2;
            C[(size_t)(r + 8) * ldc + cc + 1] = v3;
        }
    }
}

// ---------------- 64x64 tile (unchanged, for tails) ----------------
#define SA64(b,r,c) sA[(b)*(64*20) + (r)*20 + (c)]
#define SB64(b,r,c) sB[(b)*(64*20) + (r)*20 + (c)]

__device__ __forceinline__
void tf32_tile64(const float* __restrict__ A, int lda,
                 const float* __restrict__ Wt, const float* __restrict__ bias,
                 float* __restrict__ C, int ldc, int row0, int relu,
                 unsigned* sA, unsigned* sB) {
    int tid = threadIdx.x;
    int lane = tid & 31, warp = tid >> 5;
    int wm = warp & 1, wn = warp >> 1;
    int g4 = lane >> 2, l4 = lane & 3;
    int r = tid >> 2, c4 = tid & 3;

    float c[2][2][4];
#pragma unroll
    for (int mt = 0; mt < 2; mt++)
#pragma unroll
        for (int nt = 0; nt < 2; nt++)
#pragma unroll
            for (int i = 0; i < 4; i++) c[mt][nt][i] = 0.f;

    {
        float4 v = *(const float4*)&A[(size_t)(row0 + r) * lda + c4 * 4];
        SA64(0, r, c4 * 4 + 0) = f2tf(v.x); SA64(0, r, c4 * 4 + 1) = f2tf(v.y);
        SA64(0, r, c4 * 4 + 2) = f2tf(v.z); SA64(0, r, c4 * 4 + 3) = f2tf(v.w);
        float4 w = *(const float4*)&Wt[(size_t)r * 256 + c4 * 4];
        SB64(0, r, c4 * 4 + 0) = f2tf(w.x); SB64(0, r, c4 * 4 + 1) = f2tf(w.y);
        SB64(0, r, c4 * 4 + 2) = f2tf(w.z); SB64(0, r, c4 * 4 + 3) = f2tf(w.w);
    }
    __syncthreads();

    for (int ch = 0; ch < 16; ch++) {
        int buf = ch & 1;
        float4 pa, pb;
        if (ch < 15) {
            int k0 = (ch + 1) * 16;
            pa = *(const float4*)&A[(size_t)(row0 + r) * lda + k0 + c4 * 4];
            pb = *(const float4*)&Wt[(size_t)r * 256 + k0 + c4 * 4];
        }
#pragma unroll
        for (int kk = 0; kk < 2; kk++) {
            unsigned af[2][4], bf[2][2];
#pragma unroll
            for (int mt = 0; mt < 2; mt++) {
                int ar = wm * 32 + mt * 16 + g4;
                int ac = kk * 8 + l4;
                af[mt][0] = SA64(buf, ar, ac);
                af[mt][1] = SA64(buf, ar + 8, ac);
                af[mt][2] = SA64(buf, ar, ac + 4);
                af[mt][3] = SA64(buf, ar + 8, ac + 4);
            }
#pragma unroll
            for (int nt = 0; nt < 2; nt++) {
                int br = wn * 16 + nt * 8 + g4;
                bf[nt][0] = SB64(buf, br, kk * 8 + l4);
                bf[nt][1] = SB64(buf, br, kk * 8 + l4 + 4);
            }
#pragma unroll
            for (int mt = 0; mt < 2; mt++)
#pragma unroll
                for (int nt = 0; nt < 2; nt++) {
                    asm volatile(
                        "mma.sync.aligned.m16n8k8.row.col.f32.tf32.tf32.f32 "
                        "{%0,%1,%2,%3}, {%4,%5,%6,%7}, {%8,%9}, {%0,%1,%2,%3};"
                        : "+f"(c[mt][nt][0]), "+f"(c[mt][nt][1]),
                          "+f"(c[mt][nt][2]), "+f"(c[mt][nt][3])
                        : "r"(af[mt][0]), "r"(af[mt][1]), "r"(af[mt][2]), "r"(af[mt][3]),
                          "r"(bf[nt][0]), "r"(bf[nt][1]));
                }
        }
        if (ch < 15) {
            int nb = buf ^ 1;
            SA64(nb, r, c4 * 4 + 0) = f2tf(pa.x); SA64(nb, r, c4 * 4 + 1) = f2tf(pa.y);
            SA64(nb, r, c4 * 4 + 2) = f2tf(pa.z); SA64(nb, r, c4 * 4 + 3) = f2tf(pa.w);
            SB64(nb, r, c4 * 4 + 0) = f2tf(pb.x); SB64(nb, r, c4 * 4 + 1) = f2tf(pb.y);
            SB64(nb, r, c4 * 4 + 2) = f2tf(pb.z); SB64(nb, r, c4 * 4 + 3) = f2tf(pb.w);
        }
        __syncthreads();
    }

#pragma unroll
    for (int mt = 0; mt < 2; mt++) {
        int rr = row0 + wm * 32 + mt * 16 + g4;
#pragma unroll
        for (int nt = 0; nt < 2; nt++) {
            int cc = wn * 16 + nt * 8 + 2 * l4;
            float b0v = bias[cc], b1v = bias[cc + 1];
            float v0 = c[mt][nt][0] + b0v, v1 = c[mt][nt][1] + b1v;
            float v2 = c[mt][nt][2] + b0v, v3 = c[mt][nt][3] + b1v;
            if (relu) {
                v0 = fmaxf(v0, 0.f); v1 = fmaxf(v1, 0.f);
                v2 = fmaxf(v2, 0.f); v3 = fmaxf(v3, 0.f);
            }
            C[(size_t)rr * ldc + cc] = v0;
            C[(size_t)rr * ldc + cc + 1] = v1;
            C[(size_t)(rr + 8) * ldc + cc] = v2;
            C[(size_t)(rr + 8) * ldc + cc + 1] = v3;
        }
    }
}

// layer-1 projection: grid (20, 4) — KC32 128x64 (measured good)
__global__ __launch_bounds__(256)
void proj_tf32(const float* __restrict__ y, const float* __restrict__ w1,
               const float* __restrict__ bias1, float* __restrict__ seq) {
    __shared__ unsigned sA[2 * 128 * 32], sB[2 * 64 * 32];
    int h = blockIdx.y;
    tf32_tile128(y + h * kFD, 4 * kFD,
                 w1 + (size_t)h * 64 * kFD, bias1 + h * 64,
                 seq + h * 64, kFD, blockIdx.x * 128, 1, sA, sB);
}

// q+kv projection: grid (20, 5). by<4: kv 128-col tiles; by==4: q (8 blocks).
__global__ __launch_bounds__(256)
void qkv_tf32(const float* __restrict__ seq, const float* __restrict__ inw,
              const float* __restrict__ inb, float* __restrict__ kv,
              float* __restrict__ q4) {
    __shared__ unsigned sA[2 * 128 * 20], sB[2 * 128 * 20];
    int by = blockIdx.y, bx = blockIdx.x;
    if (by < 4) {
        tf32_tile128x128(seq, kFD,
                         inw + (size_t)(256 + by * 128) * kFD, inb + 256 + by * 128,
                         kv + by * 128, 2 * kFD, bx * 128, 0, sA, sB);
    } else {
        if (bx >= 8) return;
        int rt = bx & 3, ct = bx >> 2;
        tf32_tile128x128(seq + 4 * kFD, kT * kFD,
                         inw + (size_t)ct * 128 * kFD, inb + ct * 128,
                         q4 + ct * 128, kFD, rt * 128, 0, sA, sB);
    }
}

// out_proj: grid (8, 4)
__global__ __launch_bounds__(256)
void outproj_tf32(const float* __restrict__ ctx4, const float* __restrict__ outw,
                  const float* __restrict__ outb, float* __restrict__ feat) {
    __shared__ unsigned sA[2 * 64 * 20], sB[2 * 64 * 20];
    int ct = blockIdx.y;
    tf32_tile64(ctx4, kFD, outw + (size_t)ct * 64 * kFD, outb + ct * 64,
                feat + ct * 64, kFD, blockIdx.x * 64, 0, sA, sB);
}

// heads: grid (8, 5)
__global__ __launch_bounds__(256)
void heads_tf32(const float* __restrict__ feat,
                const float* __restrict__ wmean, const float* __restrict__ bmean,
                const float* __restrict__ wlogv, const float* __restrict__ blogv,
                const float* __restrict__ wbel,  const float* __restrict__ bbel,
                float* __restrict__ out, float* __restrict__ blog) {
    __shared__ unsigned sA[2 * 64 * 20], sB[2 * 64 * 20];
    int by = blockIdx.y;
    int row0 = blockIdx.x * 64;
    if (by < 2) {
        tf32_tile64(feat, kFD, wmean + (size_t)by * 64 * kFD, bmean + by * 64,
                    out + by * 64, kLAT, row0, 0, sA, sB);
        return;
    }
    if (by < 4) {
        int ct = by - 2;
        tf32_tile64(feat, kFD, wlogv + (size_t)ct * 64 * kFD, blogv + ct * 64,
                    out + (size_t)kB * kLAT + ct * 64, kLAT, row0, 0, sA, sB);
        return;
    }
    tf32_tile64(feat, kFD, wbel, bbel, blog, kS, row0, 0, sA, sB);
    __syncthreads();
    int tid = threadIdx.x;
    int r = row0 + (tid >> 2);
    int q = tid & 3;
    float v[16];
    float mx = -1e30f;
#pragma unroll
    for (int i = 0; i < 4; i++) {
        float4 x = *(const float4*)&blog[(size_t)r * kS + q * 16 + i * 4];
        v[i * 4 + 0] = x.x; v[i * 4 + 1] = x.y; v[i * 4 + 2] = x.z; v[i * 4 + 3] = x.w;
        mx = fmaxf(fmaxf(fmaxf(mx, x.x), fmaxf(x.y, x.z)), x.w);
    }
    mx = fmaxf(mx, __shfl_xor_sync(0xffffffffu, mx, 1));
    mx = fmaxf(mx, __shfl_xor_sync(0xffffffffu, mx, 2));
    float sum = 0.f;
#pragma unroll
    for (int i = 0; i < 16; i++) { v[i] = __expf(v[i] - mx); sum += v[i]; }
    sum += __shfl_xor_sync(0xffffffffu, sum, 1);
    sum += __shfl_xor_sync(0xffffffffu, sum, 2);
    float inv = 1.f / sum;
    float* ob = out + (size_t)2 * kB * kLAT;
#pragma unroll
    for (int i = 0; i < 16; i++)
        ob[(size_t)r * kS + q * 16 + i] = v[i] * inv;
}

// ===================================================================
// Attention (unchanged)
// ===================================================================
__global__ __launch_bounds__(256)
void attn_kernel(const float* __restrict__ kv, const float* __restrict__ q4g,
                 float* __restrict__ ctx4) {
    int b = blockIdx.x;
    __shared__ float ks[kT][256], vs[kT][256], q4[256];
    __shared__ float sc[4][kT], attnw[4][kT];
    int tid = threadIdx.x;
#pragma unroll
    for (int t = 0; t < kT; t++) {
        size_t base = ((size_t)(b * kT + t)) * (2 * kFD);
        ks[t][tid] = kv[base + tid];
        vs[t][tid] = kv[base + kFD + tid];
    }
    q4[tid] = q4g[(size_t)b * kFD + tid];
    __syncthreads();
    int warp = tid >> 5, lane = tid & 31;
    for (int p = warp; p < 4 * kT; p += 8) {
        int h = p / kT, kt = p % kT;
        float s = 0.f;
        for (int d = lane; d < 64; d += 32) s += q4[h * 64 + d] * ks[kt][h * 64 + d];
#pragma unroll
        for (int m = 16; m; m >>= 1) s += __shfl_xor_sync(0xffffffffu, s, m);
        if (lane == 0) sc[h][kt] = s * 0.125f;
    }
    __syncthreads();
    if (tid < 4) {
        int h = tid;
        float mx = -1e30f;
#pragma unroll
        for (int kt = 0; kt < kT; kt++) mx = fmaxf(mx, sc[h][kt]);
        float e[kT], sum = 0.f;
#pragma unroll
        for (int kt = 0; kt < kT; kt++) { e[kt] = __expf(sc[h][kt] - mx); sum += e[kt]; }
#pragma unroll
        for (int kt = 0; kt < kT; kt++) attnw[h][kt] = e[kt] / sum;
    }
    __syncthreads();
    int h = tid >> 6;
    float acc = 0.f;
#pragma unroll
    for (int kt = 0; kt < kT; kt++) acc += attnw[h][kt] * vs[kt][tid];
    ctx4[(size_t)b * kFD + tid] = acc;
}

// ===================================================================
extern "C" void kernel_launch(void* const* d_in, const int* in_sizes, int n_in,
                              void* d_out, int out_size) {
    const float* signals = (const float*)d_in[0];
    const float* nact    = (const float*)d_in[1];
    const float* w0      = (const float*)d_in[2];
    const float* asrc0   = (const float*)d_in[3];
    const float* adst0   = (const float*)d_in[4];
    const float* bias0   = (const float*)d_in[5];
    const float* w1      = (const float*)d_in[6];
    const float* asrc1   = (const float*)d_in[7];
    const float* adst1   = (const float*)d_in[8];
    const float* bias1   = (const float*)d_in[9];
    const float* inw     = (const float*)d_in[10];
    const float* inb     = (const float*)d_in[11];
    const float* outw    = (const float*)d_in[12];
    const float* outb    = (const float*)d_in[13];
    const float* wmean   = (const float*)d_in[14];
    const float* bmean   = (const float*)d_in[15];
    const float* wlogv   = (const float*)d_in[16];
    const float* blogv   = (const float*)d_in[17];
    const float* wbel    = (const float*)d_in[18];
    const float* bbel    = (const float*)d_in[19];
    float* out = (float*)d_out;

    float *y, *seq, *kv, *q4, *ctx4, *feat, *blg, *v1, *u0, *w0t, *sigp;
    cudaGetSymbolAddress((void**)&y,    g_y);
    cudaGetSymbolAddress((void**)&seq,  g_seq);
    cudaGetSymbolAddress((void**)&kv,   g_kv);
    cudaGetSymbolAddress((void**)&q4,   g_q4);
    cudaGetSymbolAddress((void**)&ctx4, g_ctx4);
    cudaGetSymbolAddress((void**)&feat, g_feat);
    cudaGetSymbolAddress((void**)&blg,  g_blog);
    cudaGetSymbolAddress((void**)&v1,   g_v1);
    cudaGetSymbolAddress((void**)&u0,   g_u0);
    cudaGetSymbolAddress((void**)&w0t,  g_w0t);
    cudaGetSymbolAddress((void**)&sigp, g_sigp);

    // 1. prep
    prep_kernel<<<251, 256>>>(w1, asrc1, adst1, w0, asrc0, adst0, signals,
                              v1, w0t, u0, sigp);
    // 2. GNN phase 1 -> y
    gnn_phase1<<<kT * kB, 256>>>(signals, nact, w0t, u0, bias0, v1, sigp, y);
    // 3. layer-1 projection (tf32, 128x64 KC32)
    proj_tf32<<<dim3(kB * kT / 128, 4), 256>>>(y, w1, bias1, seq);
    // 4. q + kv projection (tf32, 128x128 KC16)
    qkv_tf32<<<dim3(kB * kT / 128, 5), 256>>>(seq, inw, inb, kv, q4);
    // 5. attention
    attn_kernel<<<kB, 256>>>(kv, q4, ctx4);
    // 6. out_proj
    outproj_tf32<<<dim3(kB / 64, 4), 256>>>(ctx4, outw, outb, feat);
    // 7. heads
    heads_tf32<<<dim3(kB / 64, 5), 256>>>(feat, wmean, bmean, wlogv, blogv, wbel, bbel,
                                          out, blg);
}

// round 15
// speedup vs baseline: 1.2838x; 1.2838x over previous
#include <cuda_runtime.h>
#include <math.h>

static constexpr int kT = 5, kB = 512, kNA = 16, kS = 64, kA = 16;
static constexpr int kHID = 64, kH = 4, kFD = 256, kLAT = 128;
static constexpr int kN = kB * kNA;
static constexpr int kFIN = 80;

// -------- scratch (static device globals) --------
__device__ float g_y   [(size_t)kB * kT * 4 * kFD];
__device__ float g_seq [(size_t)kB * kT * kFD];
__device__ float g_kv  [(size_t)kB * kT * 2 * kFD];
__device__ float g_q4  [(size_t)kB * kFD];
__device__ float g_ctx4[(size_t)kB * kFD];
__device__ float g_feat[(size_t)kB * kFD];
__device__ float g_blog[(size_t)kB * kS];
__device__ float g_v1  [2 * 4 * kFD];
__device__ float g_u0  [2 * 4 * kFIN];
__device__ float g_w0t [kFIN * kFD];
__device__ float g_sigp[(size_t)kT * kB * kFD];
__device__ float g_w1r [kFD * kFD];        // tf32-rounded w1
__device__ float g_inwr[3 * kFD * kFD];    // tf32-rounded in_proj_w

__device__ __forceinline__ unsigned f2tf(float x) {
    unsigned u;
    asm("cvt.rna.tf32.f32 %0, %1;" : "=r"(u) : "f"(x));
    return u;
}
__device__ __forceinline__ float f2tf_f(float x) { return __uint_as_float(f2tf(x)); }

// ===================================================================
// Prep: v1 + w0t + u0 + sigproj GEMM + rounded weight copies. grid = 507.
// ===================================================================
__global__ __launch_bounds__(256)
void prep_kernel(const float* __restrict__ w1, const float* __restrict__ asrc1,
                 const float* __restrict__ adst1, const float* __restrict__ w0,
                 const float* __restrict__ asrc0, const float* __restrict__ adst0,
                 const float* __restrict__ signals, const float* __restrict__ inw,
                 float* __restrict__ v1, float* __restrict__ w0t,
                 float* __restrict__ u0, float* __restrict__ sigp,
                 float* __restrict__ w1r, float* __restrict__ inwr) {
    int bid = blockIdx.x, tid = threadIdx.x;
    if (bid < 8) {
        int idx = bid * 256 + tid;
        int which = idx >> 10;
        int h = (idx >> 8) & 3;
        int k = idx & 255;
        const float* a = which ? adst1 : asrc1;
        float acc = 0.f;
#pragma unroll
        for (int c = 0; c < 64; c++)
            acc += a[h * 64 + c] * w1[(size_t)(h * 64 + c) * kFD + k];
        v1[which * 1024 + h * 256 + k] = acc;
        return;
    }
    if (bid < 88) {
        int c = bid - 8;
        w0t[(size_t)c * kFD + tid] = w0[(size_t)tid * kFIN + c];
        return;
    }
    if (bid < 91) {
        int idx = (bid - 88) * 256 + tid;
        if (idx >= 640) return;
        int which = idx / 320;
        int r = idx % 320;
        int h = r / 80, f = r % 80;
        const float* a = which ? adst0 : asrc0;
        float acc = 0.f;
#pragma unroll
        for (int c = 0; c < 64; c++)
            acc += a[h * 64 + c] * w0[(size_t)(h * 64 + c) * kFIN + f];
        u0[idx] = acc;
        return;
    }
    if (bid < 251) {
        // sigproj: 16 rows per block
        __shared__ float sigs[16][64];
        int r0 = (bid - 91) * 16;
#pragma unroll
        for (int i = 0; i < 4; i++) {
            int idx = tid + i * 256;
            sigs[idx >> 6][idx & 63] = signals[(size_t)(r0 + (idx >> 6)) * kS + (idx & 63)];
        }
        __syncthreads();
        float acc[16];
#pragma unroll
        for (int i = 0; i < 16; i++) acc[i] = 0.f;
        for (int c = 0; c < 64; c++) {
            float w = w0[(size_t)tid * kFIN + c];
#pragma unroll
            for (int i = 0; i < 16; i++) acc[i] += sigs[i][c] * w;
        }
#pragma unroll
        for (int i = 0; i < 16; i++)
            sigp[(size_t)(r0 + i) * kFD + tid] = acc[i];
        return;
    }
    // rounded weight copies: 256 blocks x 1024 elems
    {
        size_t base = (size_t)(bid - 251) * 1024;
#pragma unroll
        for (int i = 0; i < 4; i++) {
            size_t idx = base + tid + i * 256;
            if (idx < (size_t)kFD * kFD)
                w1r[idx] = f2tf_f(w1[idx]);
            else {
                size_t j = idx - (size_t)kFD * kFD;
                inwr[j] = f2tf_f(inw[j]);
            }
        }
    }
}

// ===================================================================
// GNN phase 1 (R13 version — vs1/vd1 staged in smem). 2560 blocks.
// Phase-8 writes y pre-rounded to tf32 (consumed only by proj).
// ===================================================================
__global__ __launch_bounds__(256)
void gnn_phase1(const float* __restrict__ signals, const float* __restrict__ nact,
                const float* __restrict__ w0t, const float* __restrict__ u0,
                const float* __restrict__ bias0, const float* __restrict__ v1,
                const float* __restrict__ sigp, float* __restrict__ y) {
    __shared__ float acts[16][16];
    __shared__ float sig[64];
    __shared__ float us[320], ud[320];
    __shared__ float es0[16][4], ed0[16][4];
    __shared__ float alpha0[16][16][4];
    __shared__ float beta[16][4][16];
    __shared__ float gam[16][4];
    __shared__ float x1s[16][256];
    __shared__ float vs1[4][256], vd1[4][256];
    __shared__ float es1[16][4], ed1s[4], alpha1[16][4];

    int bid = blockIdx.x;
    int t = bid >> 9;
    int g = bid & 511;
    int tid = threadIdx.x;

    float Wa[16];
#pragma unroll
    for (int k = 0; k < 16; k++) Wa[k] = w0t[(size_t)(64 + k) * kFD + tid];
    float b0 = bias0[tid];
    float sp = sigp[(size_t)bid * kFD + tid];

    acts[tid >> 4][tid & 15] = nact[((size_t)t * kB + g) * (kNA * kA) + tid];
    if (tid < 64) sig[tid] = signals[((size_t)t * kB + g) * kS + tid];
#pragma unroll
    for (int i = 0; i < 2; i++) {
        int f = tid + i * 256;
        if (f < 320) { us[f] = u0[f]; ud[f] = u0[320 + f]; }
    }
#pragma unroll
    for (int h = 0; h < 4; h++) {
        vs1[h][tid] = v1[h * 256 + tid];
        vd1[h][tid] = v1[1024 + h * 256 + tid];
    }
    __syncthreads();

    if (tid < 128) {
        int which = tid >> 6;
        int p = tid & 63;
        int j = p >> 2, h = p & 3;
        const float* u = which ? ud : us;
        float e = 0.f;
#pragma unroll
        for (int k = 0; k < 16; k++) e += acts[j][k] * u[h * 80 + 64 + k];
        if (j == 0) {
#pragma unroll
            for (int c = 0; c < 64; c++) e += sig[c] * u[h * 80 + c];
        }
        if (which) ed0[j][h] = e; else es0[j][h] = e;
    }
    __syncthreads();

    if (tid < 64) {
        int n = tid >> 2, h = tid & 3;
        float base = ed0[n][h];
        float ev[16];
        float mx = -1e30f;
#pragma unroll
        for (int j = 0; j < 16; j++) {
            float e = es0[j][h] + base;
            e = e > 0.f ? e : 0.2f * e;
            ev[j] = e;
            mx = fmaxf(mx, e);
        }
        float sum = 0.f;
#pragma unroll
        for (int j = 0; j < 16; j++) { ev[j] = __expf(ev[j] - mx); sum += ev[j]; }
        float inv = 1.f / sum;
#pragma unroll
        for (int j = 0; j < 16; j++) alpha0[n][j][h] = ev[j] * inv;
    }
    __syncthreads();

    {
        int n = tid >> 4, h = (tid >> 2) & 3, kg = tid & 3;
        float bacc[4] = {0.f, 0.f, 0.f, 0.f};
#pragma unroll
        for (int j = 0; j < 16; j++) {
            float a = alpha0[n][j][h];
#pragma unroll
            for (int kk = 0; kk < 4; kk++) bacc[kk] += a * acts[j][kg * 4 + kk];
        }
#pragma unroll
        for (int kk = 0; kk < 4; kk++) beta[n][h][kg * 4 + kk] = bacc[kk];
        if (kg == 0) gam[n][h] = alpha0[n][0][h];
    }
    __syncthreads();

    int hd = tid >> 6;
    float x1r[16];
    {
#pragma unroll
        for (int n = 0; n < 16; n++) {
            float acc = gam[n][hd] * sp;
#pragma unroll
            for (int k = 0; k < 16; k++) acc += beta[n][hd][k] * Wa[k];
            acc = fmaxf(acc + b0, 0.f);
            x1r[n] = acc;
            x1s[n][tid] = acc;
        }
    }
    __syncthreads();

    {
        int p = tid >> 2, q = tid & 3;
        int j = p >> 2, h = p & 3;
        float acc = 0.f;
#pragma unroll
        for (int c = q * 64; c < q * 64 + 64; c++) acc += x1s[j][c] * vs1[h][c];
        acc += __shfl_xor_sync(0xffffffffu, acc, 1);
        acc += __shfl_xor_sync(0xffffffffu, acc, 2);
        if (q == 0) es1[j][h] = acc;
    }
    if (tid < 32) {
        int h = tid >> 3, q = tid & 7;
        float acc = 0.f;
#pragma unroll
        for (int c = q * 32; c < q * 32 + 32; c++) acc += x1s[0][c] * vd1[h][c];
        acc += __shfl_xor_sync(0xffffffffu, acc, 1);
        acc += __shfl_xor_sync(0xffffffffu, acc, 2);
        acc += __shfl_xor_sync(0xffffffffu, acc, 4);
        if (q == 0) ed1s[h] = acc;
    }
    __syncthreads();

    if (tid < 4) {
        int h = tid;
        float base = ed1s[h];
        float ev[16];
        float mx = -1e30f;
#pragma unroll
        for (int j = 0; j < 16; j++) {
            float e = es1[j][h] + base;
            e = e > 0.f ? e : 0.2f * e;
            ev[j] = e;
            mx = fmaxf(mx, e);
        }
        float sum = 0.f;
#pragma unroll
        for (int j = 0; j < 16; j++) { ev[j] = __expf(ev[j] - mx); sum += ev[j]; }
        float inv = 1.f / sum;
#pragma unroll
        for (int j = 0; j < 16; j++) alpha1[j][h] = ev[j] * inv;
    }
    __syncthreads();

#pragma unroll
    for (int h = 0; h < 4; h++) {
        float acc = 0.f;
#pragma unroll
        for (int j = 0; j < 16; j++) acc += alpha1[j][h] * x1r[j];
        y[(((size_t)g * kT + t) * 4 + h) * kFD + tid] = f2tf_f(acc);  // pre-rounded
    }
}

// ===================================================================
// 128x64 tile, K-chunk 32, XOR-swizzled smem (R13, measured good).
// pre=1: inputs already tf32-rounded -> raw bit loads (no cvt in loop).
// ===================================================================
#define IA(b,r,c4) ((b)*4096 + (r)*32 + 4*((c4) ^ ((r)&7)))
#define IB(b,r,c4) ((b)*2048 + (r)*32 + 4*((c4) ^ ((r)&7)))

__device__ __forceinline__
void tf32_tile128(const float* __restrict__ A, int lda,
                  const float* __restrict__ Wt, const float* __restrict__ bias,
                  float* __restrict__ C, int ldc, int row0, int relu, int pre,
                  unsigned* sA, unsigned* sB) {
    int tid = threadIdx.x;
    int lane = tid & 31, warp = tid >> 5;
    int wm = warp & 3, wn = warp >> 2;
    int g4 = lane >> 2, l4 = lane & 3;

    float c[2][4][4];
#pragma unroll
    for (int mt = 0; mt < 2; mt++)
#pragma unroll
        for (int nt = 0; nt < 4; nt++)
#pragma unroll
            for (int i = 0; i < 4; i++) c[mt][nt][i] = 0.f;

#define CVT(x) (pre ? __float_as_uint(x) : f2tf(x))
#pragma unroll
    for (int i = 0; i < 4; i++) {
        int idx = tid + i * 256;
        int r = idx >> 3, c4 = idx & 7;
        float4 v = *(const float4*)&A[(size_t)(row0 + r) * lda + c4 * 4];
        unsigned* p = &sA[IA(0, r, c4)];
        p[0] = CVT(v.x); p[1] = CVT(v.y); p[2] = CVT(v.z); p[3] = CVT(v.w);
    }
#pragma unroll
    for (int i = 0; i < 2; i++) {
        int idx = tid + i * 256;
        int r = idx >> 3, c4 = idx & 7;
        float4 w = *(const float4*)&Wt[(size_t)r * 256 + c4 * 4];
        unsigned* p = &sB[IB(0, r, c4)];
        p[0] = CVT(w.x); p[1] = CVT(w.y); p[2] = CVT(w.z); p[3] = CVT(w.w);
    }
    __syncthreads();

    for (int ch = 0; ch < 8; ch++) {
        int buf = ch & 1;
        float4 pa[4], pw[2];
        if (ch < 7) {
            int k0 = (ch + 1) * 32;
#pragma unroll
            for (int i = 0; i < 4; i++) {
                int idx = tid + i * 256;
                int r = idx >> 3, c4 = idx & 7;
                pa[i] = *(const float4*)&A[(size_t)(row0 + r) * lda + k0 + c4 * 4];
            }
#pragma unroll
            for (int i = 0; i < 2; i++) {
                int idx = tid + i * 256;
                int r = idx >> 3, c4 = idx & 7;
                pw[i] = *(const float4*)&Wt[(size_t)r * 256 + k0 + c4 * 4];
            }
        }
#pragma unroll
        for (int kk = 0; kk < 4; kk++) {
            unsigned af[2][4], bf[4][2];
#pragma unroll
            for (int mt = 0; mt < 2; mt++) {
                int ar = wm * 32 + mt * 16 + g4;
                af[mt][0] = sA[IA(buf, ar,     kk * 2    ) + l4];
                af[mt][1] = sA[IA(buf, ar + 8, kk * 2    ) + l4];
                af[mt][2] = sA[IA(buf, ar,     kk * 2 + 1) + l4];
                af[mt][3] = sA[IA(buf, ar + 8, kk * 2 + 1) + l4];
            }
#pragma unroll
            for (int nt = 0; nt < 4; nt++) {
                int br = wn * 32 + nt * 8 + g4;
                bf[nt][0] = sB[IB(buf, br, kk * 2    ) + l4];
                bf[nt][1] = sB[IB(buf, br, kk * 2 + 1) + l4];
            }
#pragma unroll
            for (int mt = 0; mt < 2; mt++)
#pragma unroll
                for (int nt = 0; nt < 4; nt++) {
                    asm volatile(
                        "mma.sync.aligned.m16n8k8.row.col.f32.tf32.tf32.f32 "
                        "{%0,%1,%2,%3}, {%4,%5,%6,%7}, {%8,%9}, {%0,%1,%2,%3};"
                        : "+f"(c[mt][nt][0]), "+f"(c[mt][nt][1]),
                          "+f"(c[mt][nt][2]), "+f"(c[mt][nt][3])
                        : "r"(af[mt][0]), "r"(af[mt][1]), "r"(af[mt][2]), "r"(af[mt][3]),
                          "r"(bf[nt][0]), "r"(bf[nt][1]));
                }
        }
        if (ch < 7) {
            int nb = buf ^ 1;
#pragma unroll
            for (int i = 0; i < 4; i++) {
                int idx = tid + i * 256;
                int r = idx >> 3, c4 = idx & 7;
                unsigned* p = &sA[IA(nb, r, c4)];
                p[0] = CVT(pa[i].x); p[1] = CVT(pa[i].y);
                p[2] = CVT(pa[i].z); p[3] = CVT(pa[i].w);
            }
#pragma unroll
            for (int i = 0; i < 2; i++) {
                int idx = tid + i * 256;
                int r = idx >> 3, c4 = idx & 7;
                unsigned* p = &sB[IB(nb, r, c4)];
                p[0] = CVT(pw[i].x); p[1] = CVT(pw[i].y);
                p[2] = CVT(pw[i].z); p[3] = CVT(pw[i].w);
            }
        }
        __syncthreads();
    }
#undef CVT

#pragma unroll
    for (int mt = 0; mt < 2; mt++) {
        int r = row0 + wm * 32 + mt * 16 + g4;
#pragma unroll
        for (int nt = 0; nt < 4; nt++) {
            int cc = wn * 32 + nt * 8 + 2 * l4;
            float b0v = bias[cc], b1v = bias[cc + 1];
            float v0 = c[mt][nt][0] + b0v, v1 = c[mt][nt][1] + b1v;
            float v2 = c[mt][nt][2] + b0v, v3 = c[mt][nt][3] + b1v;
            if (relu) {
                v0 = fmaxf(f2tf_f(fmaxf(v0, 0.f)), 0.f);   // pre-round seq for qkv
                v1 = fmaxf(f2tf_f(fmaxf(v1, 0.f)), 0.f);
                v2 = fmaxf(f2tf_f(fmaxf(v2, 0.f)), 0.f);
                v3 = fmaxf(f2tf_f(fmaxf(v3, 0.f)), 0.f);
            }
            C[(size_t)r * ldc + cc] = v0;
            C[(size_t)r * ldc + cc + 1] = v1;
            C[(size_t)(r + 8) * ldc + cc] = v2;
            C[(size_t)(r + 8) * ldc + cc + 1] = v3;
        }
    }
}

// ---------------- 64x64 tile (R9/R13 config, unchanged; f2tf path) --------
#define SA64(b,r,c) sA[(b)*(64*20) + (r)*20 + (c)]
#define SB64(b,r,c) sB[(b)*(64*20) + (r)*20 + (c)]

__device__ __forceinline__
void tf32_tile64(const float* __restrict__ A, int lda,
                 const float* __restrict__ Wt, const float* __restrict__ bias,
                 float* __restrict__ C, int ldc, int row0, int relu,
                 unsigned* sA, unsigned* sB) {
    int tid = threadIdx.x;
    int lane = tid & 31, warp = tid >> 5;
    int wm = warp & 1, wn = warp >> 1;
    int g4 = lane >> 2, l4 = lane & 3;
    int r = tid >> 2, c4 = tid & 3;

    float c[2][2][4];
#pragma unroll
    for (int mt = 0; mt < 2; mt++)
#pragma unroll
        for (int nt = 0; nt < 2; nt++)
#pragma unroll
            for (int i = 0; i < 4; i++) c[mt][nt][i] = 0.f;

    {
        float4 v = *(const float4*)&A[(size_t)(row0 + r) * lda + c4 * 4];
        SA64(0, r, c4 * 4 + 0) = f2tf(v.x); SA64(0, r, c4 * 4 + 1) = f2tf(v.y);
        SA64(0, r, c4 * 4 + 2) = f2tf(v.z); SA64(0, r, c4 * 4 + 3) = f2tf(v.w);
        float4 w = *(const float4*)&Wt[(size_t)r * 256 + c4 * 4];
        SB64(0, r, c4 * 4 + 0) = f2tf(w.x); SB64(0, r, c4 * 4 + 1) = f2tf(w.y);
        SB64(0, r, c4 * 4 + 2) = f2tf(w.z); SB64(0, r, c4 * 4 + 3) = f2tf(w.w);
    }
    __syncthreads();

    for (int ch = 0; ch < 16; ch++) {
        int buf = ch & 1;
        float4 pa, pb;
        if (ch < 15) {
            int k0 = (ch + 1) * 16;
            pa = *(const float4*)&A[(size_t)(row0 + r) * lda + k0 + c4 * 4];
            pb = *(const float4*)&Wt[(size_t)r * 256 + k0 + c4 * 4];
        }
#pragma unroll
        for (int kk = 0; kk < 2; kk++) {
            unsigned af[2][4], bf[2][2];
#pragma unroll
            for (int mt = 0; mt < 2; mt++) {
                int ar = wm * 32 + mt * 16 + g4;
                int ac = kk * 8 + l4;
                af[mt][0] = SA64(buf, ar, ac);
                af[mt][1] = SA64(buf, ar + 8, ac);
                af[mt][2] = SA64(buf, ar, ac + 4);
                af[mt][3] = SA64(buf, ar + 8, ac + 4);
            }
#pragma unroll
            for (int nt = 0; nt < 2; nt++) {
                int br = wn * 16 + nt * 8 + g4;
                bf[nt][0] = SB64(buf, br, kk * 8 + l4);
                bf[nt][1] = SB64(buf, br, kk * 8 + l4 + 4);
            }
#pragma unroll
            for (int mt = 0; mt < 2; mt++)
#pragma unroll
                for (int nt = 0; nt < 2; nt++) {
                    asm volatile(
                        "mma.sync.aligned.m16n8k8.row.col.f32.tf32.tf32.f32 "
                        "{%0,%1,%2,%3}, {%4,%5,%6,%7}, {%8,%9}, {%0,%1,%2,%3};"
                        : "+f"(c[mt][nt][0]), "+f"(c[mt][nt][1]),
                          "+f"(c[mt][nt][2]), "+f"(c[mt][nt][3])
                        : "r"(af[mt][0]), "r"(af[mt][1]), "r"(af[mt][2]), "r"(af[mt][3]),
                          "r"(bf[nt][0]), "r"(bf[nt][1]));
                }
        }
        if (ch < 15) {
            int nb = buf ^ 1;
            SA64(nb, r, c4 * 4 + 0) = f2tf(pa.x); SA64(nb, r, c4 * 4 + 1) = f2tf(pa.y);
            SA64(nb, r, c4 * 4 + 2) = f2tf(pa.z); SA64(nb, r, c4 * 4 + 3) = f2tf(pa.w);
            SB64(nb, r, c4 * 4 + 0) = f2tf(pb.x); SB64(nb, r, c4 * 4 + 1) = f2tf(pb.y);
            SB64(nb, r, c4 * 4 + 2) = f2tf(pb.z); SB64(nb, r, c4 * 4 + 3) = f2tf(pb.w);
        }
        __syncthreads();
    }

#pragma unroll
    for (int mt = 0; mt < 2; mt++) {
        int rr = row0 + wm * 32 + mt * 16 + g4;
#pragma unroll
        for (int nt = 0; nt < 2; nt++) {
            int cc = wn * 16 + nt * 8 + 2 * l4;
            float b0v = bias[cc], b1v = bias[cc + 1];
            float v0 = c[mt][nt][0] + b0v, v1 = c[mt][nt][1] + b1v;
            float v2 = c[mt][nt][2] + b0v, v3 = c[mt][nt][3] + b1v;
            if (relu) {
                v0 = fmaxf(v0, 0.f); v1 = fmaxf(v1, 0.f);
                v2 = fmaxf(v2, 0.f); v3 = fmaxf(v3, 0.f);
            }
            C[(size_t)rr * ldc + cc] = v0;
            C[(size_t)rr * ldc + cc + 1] = v1;
            C[(size_t)(rr + 8) * ldc + cc] = v2;
            C[(size_t)(rr + 8) * ldc + cc + 1] = v3;
        }
    }
}

// layer-1 projection: grid (20, 4) — pre-rounded A (y) and B (w1r)
__global__ __launch_bounds__(256)
void proj_tf32(const float* __restrict__ y, const float* __restrict__ w1r,
               const float* __restrict__ bias1, float* __restrict__ seq) {
    __shared__ unsigned sA[2 * 128 * 32], sB[2 * 64 * 32];
    int h = blockIdx.y;
    tf32_tile128(y + h * kFD, 4 * kFD,
                 w1r + (size_t)h * 64 * kFD, bias1 + h * 64,
                 seq + h * 64, kFD, blockIdx.x * 128, 1, 1, sA, sB);
}

// q+kv projection: grid (20, 9) — pre-rounded A (seq) and B (inwr)
__global__ __launch_bounds__(256)
void qkv_tf32(const float* __restrict__ seq, const float* __restrict__ inwr,
              const float* __restrict__ inb, float* __restrict__ kv,
              float* __restrict__ q4) {
    __shared__ unsigned sA[2 * 128 * 32], sB[2 * 64 * 32];
    int by = blockIdx.y, bx = blockIdx.x;
    if (by < 8) {
        tf32_tile128(seq, kFD,
                     inwr + (size_t)(256 + by * 64) * kFD, inb + 256 + by * 64,
                     kv + by * 64, 2 * kFD, bx * 128, 0, 1, sA, sB);
    } else {
        if (bx >= 16) return;
        int rt = bx & 3, ct = bx >> 2;
        tf32_tile128(seq + 4 * kFD, kT * kFD,
                     inwr + (size_t)ct * 64 * kFD, inb + ct * 64,
                     q4 + ct * 64, kFD, rt * 128, 0, 1, sA, sB);
    }
}

// out_proj: grid (8, 4)
__global__ __launch_bounds__(256)
void outproj_tf32(const float* __restrict__ ctx4, const float* __restrict__ outw,
                  const float* __restrict__ outb, float* __restrict__ feat) {
    __shared__ unsigned sA[2 * 64 * 20], sB[2 * 64 * 20];
    int ct = blockIdx.y;
    tf32_tile64(ctx4, kFD, outw + (size_t)ct * 64 * kFD, outb + ct * 64,
                feat + ct * 64, kFD, blockIdx.x * 64, 0, sA, sB);
}

// heads: grid (8, 5)
__global__ __launch_bounds__(256)
void heads_tf32(const float* __restrict__ feat,
                const float* __restrict__ wmean, const float* __restrict__ bmean,
                const float* __restrict__ wlogv, const float* __restrict__ blogv,
                const float* __restrict__ wbel,  const float* __restrict__ bbel,
                float* __restrict__ out, float* __restrict__ blog) {
    __shared__ unsigned sA[2 * 64 * 20], sB[2 * 64 * 20];
    int by = blockIdx.y;
    int row0 = blockIdx.x * 64;
    if (by < 2) {
        tf32_tile64(feat, kFD, wmean + (size_t)by * 64 * kFD, bmean + by * 64,
                    out + by * 64, kLAT, row0, 0, sA, sB);
        return;
    }
    if (by < 4) {
        int ct = by - 2;
        tf32_tile64(feat, kFD, wlogv + (size_t)ct * 64 * kFD, blogv + ct * 64,
                    out + (size_t)kB * kLAT + ct * 64, kLAT, row0, 0, sA, sB);
        return;
    }
    tf32_tile64(feat, kFD, wbel, bbel, blog, kS, row0, 0, sA, sB);
    __syncthreads();
    int tid = threadIdx.x;
    int r = row0 + (tid >> 2);
    int q = tid & 3;
    float v[16];
    float mx = -1e30f;
#pragma unroll
    for (int i = 0; i < 4; i++) {
        float4 x = *(const float4*)&blog[(size_t)r * kS + q * 16 + i * 4];
        v[i * 4 + 0] = x.x; v[i * 4 + 1] = x.y; v[i * 4 + 2] = x.z; v[i * 4 + 3] = x.w;
        mx = fmaxf(fmaxf(fmaxf(mx, x.x), fmaxf(x.y, x.z)), x.w);
    }
    mx = fmaxf(mx, __shfl_xor_sync(0xffffffffu, mx, 1));
    mx = fmaxf(mx, __shfl_xor_sync(0xffffffffu, mx, 2));
    float sum = 0.f;
#pragma unroll
    for (int i = 0; i < 16; i++) { v[i] = __expf(v[i] - mx); sum += v[i]; }
    sum += __shfl_xor_sync(0xffffffffu, sum, 1);
    sum += __shfl_xor_sync(0xffffffffu, sum, 2);
    float inv = 1.f / sum;
    float* ob = out + (size_t)2 * kB * kLAT;
#pragma unroll
    for (int i = 0; i < 16; i++)
        ob[(size_t)r * kS + q * 16 + i] = v[i] * inv;
}

// ===================================================================
// Attention (unchanged)
// ===================================================================
__global__ __launch_bounds__(256)
void attn_kernel(const float* __restrict__ kv, const float* __restrict__ q4g,
                 float* __restrict__ ctx4) {
    int b = blockIdx.x;
    __shared__ float ks[kT][256], vs[kT][256], q4[256];
    __shared__ float sc[4][kT], attnw[4][kT];
    int tid = threadIdx.x;
#pragma unroll
    for (int t = 0; t < kT; t++) {
        size_t base = ((size_t)(b * kT + t)) * (2 * kFD);
        ks[t][tid] = kv[base + tid];
        vs[t][tid] = kv[base + kFD + tid];
    }
    q4[tid] = q4g[(size_t)b * kFD + tid];
    __syncthreads();
    int warp = tid >> 5, lane = tid & 31;
    for (int p = warp; p < 4 * kT; p += 8) {
        int h = p / kT, kt = p % kT;
        float s = 0.f;
        for (int d = lane; d < 64; d += 32) s += q4[h * 64 + d] * ks[kt][h * 64 + d];
#pragma unroll
        for (int m = 16; m; m >>= 1) s += __shfl_xor_sync(0xffffffffu, s, m);
        if (lane == 0) sc[h][kt] = s * 0.125f;
    }
    __syncthreads();
    if (tid < 4) {
        int h = tid;
        float mx = -1e30f;
#pragma unroll
        for (int kt = 0; kt < kT; kt++) mx = fmaxf(mx, sc[h][kt]);
        float e[kT], sum = 0.f;
#pragma unroll
        for (int kt = 0; kt < kT; kt++) { e[kt] = __expf(sc[h][kt] - mx); sum += e[kt]; }
#pragma unroll
        for (int kt = 0; kt < kT; kt++) attnw[h][kt] = e[kt] / sum;
    }
    __syncthreads();
    int h = tid >> 6;
    float acc = 0.f;
#pragma unroll
    for (int kt = 0; kt < kT; kt++) acc += attnw[h][kt] * vs[kt][tid];
    ctx4[(size_t)b * kFD + tid] = acc;
}

// ===================================================================
extern "C" void kernel_launch(void* const* d_in, const int* in_sizes, int n_in,
                              void* d_out, int out_size) {
    const float* signals = (const float*)d_in[0];
    const float* nact    = (const float*)d_in[1];
    const float* w0      = (const float*)d_in[2];
    const float* asrc0   = (const float*)d_in[3];
    const float* adst0   = (const float*)d_in[4];
    const float* bias0   = (const float*)d_in[5];
    const float* w1      = (const float*)d_in[6];
    const float* asrc1   = (const float*)d_in[7];
    const float* adst1   = (const float*)d_in[8];
    const float* bias1   = (const float*)d_in[9];
    const float* inw     = (const float*)d_in[10];
    const float* inb     = (const float*)d_in[11];
    const float* outw    = (const float*)d_in[12];
    const float* outb    = (const float*)d_in[13];
    const float* wmean   = (const float*)d_in[14];
    const float* bmean   = (const float*)d_in[15];
    const float* wlogv   = (const float*)d_in[16];
    const float* blogv   = (const float*)d_in[17];
    const float* wbel    = (const float*)d_in[18];
    const float* bbel    = (const float*)d_in[19];
    float* out = (float*)d_out;

    float *y, *seq, *kv, *q4, *ctx4, *feat, *blg, *v1, *u0, *w0t, *sigp, *w1r, *inwr;
    cudaGetSymbolAddress((void**)&y,    g_y);
    cudaGetSymbolAddress((void**)&seq,  g_seq);
    cudaGetSymbolAddress((void**)&kv,   g_kv);
    cudaGetSymbolAddress((void**)&q4,   g_q4);
    cudaGetSymbolAddress((void**)&ctx4, g_ctx4);
    cudaGetSymbolAddress((void**)&feat, g_feat);
    cudaGetSymbolAddress((void**)&blg,  g_blog);
    cudaGetSymbolAddress((void**)&v1,   g_v1);
    cudaGetSymbolAddress((void**)&u0,   g_u0);
    cudaGetSymbolAddress((void**)&w0t,  g_w0t);
    cudaGetSymbolAddress((void**)&sigp, g_sigp);
    cudaGetSymbolAddress((void**)&w1r,  g_w1r);
    cudaGetSymbolAddress((void**)&inwr, g_inwr);

    // 1. prep (incl. tf32-rounded weight copies)
    prep_kernel<<<507, 256>>>(w1, asrc1, adst1, w0, asrc0, adst0, signals, inw,
                              v1, w0t, u0, sigp, w1r, inwr);
    // 2. GNN phase 1 -> y (pre-rounded)
    gnn_phase1<<<kT * kB, 256>>>(signals, nact, w0t, u0, bias0, v1, sigp, y);
    // 3. layer-1 projection (tf32, 128x64 KC32, no-cvt loop)
    proj_tf32<<<dim3(kB * kT / 128, 4), 256>>>(y, w1r, bias1, seq);
    // 4. q + kv projection (tf32, 128x64 KC32, no-cvt loop)
    qkv_tf32<<<dim3(kB * kT / 128, 9), 256>>>(seq, inwr, inb, kv, q4);
    // 5. attention
    attn_kernel<<<kB, 256>>>(kv, q4, ctx4);
    // 6. out_proj
    outproj_tf32<<<dim3(kB / 64, 4), 256>>>(ctx4, outw, outb, feat);
    // 7. heads
    heads_tf32<<<dim3(kB / 64, 5), 256>>>(feat, wmean, bmean, wlogv, blogv, wbel, bbel,
                                          out, blg);
}